// round 5
// baseline (speedup 1.0000x reference)
#include <cuda_runtime.h>
#include <cstdint>
#include <math.h>

#define B_   32
#define N_   3136
#define C_   384
#define H_   8
#define HD_  48
#define NT_  196
#define EPS_ 1e-6f
#define SCALE_ 0.14433756729740643f   /* 1/sqrt(48) */

// ---------------------------------------------------------------------------
// Static device buffers (no runtime allocation).
// ---------------------------------------------------------------------------
__device__ __align__(128) float g_xn [(size_t)B_*N_*C_];
__device__ __align__(128) float g_kv [(size_t)B_*N_*2*C_];
__device__ __align__(128) float g_qc1[(size_t)B_*NT_*C_];
__device__ __align__(128) float g_hb [(size_t)B_*NT_*2*C_];
__device__ __align__(128) float g_qc2[(size_t)B_*NT_*C_];
__device__ __align__(128) float g_av [(size_t)B_*NT_*C_];
__device__ __align__(128) int   g_cent[(size_t)B_*NT_];

// ---------------------------------------------------------------------------
// Helpers
// ---------------------------------------------------------------------------
__device__ __forceinline__ float gelu_f(float x) {
    return 0.5f * x * (1.0f + erff(x * 0.70710678118654752f));
}

__device__ __forceinline__ uint32_t f2tf32(float x) {
    uint32_t r;
    asm("cvt.rna.tf32.f32 %0, %1;" : "=r"(r) : "f"(x));
    return r;
}
__device__ __forceinline__ void split_tf32(float v, uint32_t& hi, uint32_t& lo) {
    hi = f2tf32(v);
    lo = f2tf32(v - __uint_as_float(hi));
}

// m16n8k8 tf32 MMA, fp32 accumulate (sm_80+, no arch-suffix gating).
__device__ __forceinline__ void mma8(float* d, const uint4& a, const uint2& b) {
    asm volatile(
        "mma.sync.aligned.m16n8k8.row.col.f32.tf32.tf32.f32 "
        "{%0,%1,%2,%3},{%4,%5,%6,%7},{%8,%9},{%0,%1,%2,%3};"
        : "+f"(d[0]), "+f"(d[1]), "+f"(d[2]), "+f"(d[3])
        : "r"(a.x), "r"(a.y), "r"(a.z), "r"(a.w), "r"(b.x), "r"(b.y));
}

// ---------------------------------------------------------------------------
// 3xTF32 GEMM: C[M,Nn] = A[M,K] @ W[Nn,K]^T (+bias)(+gelu)
// Block 128x64, 8 warps of 32x32, BK=32, fragment-major smem staging with
// on-the-fly hi/lo TF32 split, register-prefetch double buffering.
// smem: A frag store [2buf][4ks][8mf][2p][32lane][4] uints = 16384
//       B frag store [2buf][4ks][8nf][2p][32lane][2] uints =  8192
// ---------------------------------------------------------------------------
#define GEMM_SMEM (24576 * 4)   /* 96 KB */

__device__ __forceinline__
void gemm_body(const float* __restrict__ A, const float* __restrict__ W,
               const float* __restrict__ bias, float* __restrict__ Co,
               int M, int Nn, int K, int mode) {
    extern __shared__ __align__(16) uint32_t sm[];
    uint32_t* sA = sm;            // 16384 uints
    uint32_t* sB = sm + 16384;    //  8192 uints
    int tid = threadIdx.x;
    int lane = tid & 31, warp = tid >> 5;
    int wm = warp & 3, wn = warp >> 2;
    int m0 = blockIdx.y * 128, n0 = blockIdx.x * 64;

    float acc[2][4][4];
#pragma unroll
    for (int i = 0; i < 2; i++)
#pragma unroll
        for (int j = 0; j < 4; j++)
#pragma unroll
            for (int e = 0; e < 4; e++) acc[i][j][e] = 0.f;

    // Global prefetch mapping
    int arow = tid >> 1, akb = (tid & 1) * 16;   // A: 128 rows x 32 k
    int brow = tid >> 2, bkb = (tid & 3) * 8;    // B:  64 rows x 32 k
    const float* Abase = A + (size_t)(m0 + arow) * K + akb;
    const float* Bbase = W + (size_t)(n0 + brow) * K + bkb;

    float4 aR[4], bR[2];

#define LOADG(c) do {                                                   \
        const float* _ap = Abase + (c) * 32;                            \
        aR[0] = *(const float4*)(_ap + 0);                              \
        aR[1] = *(const float4*)(_ap + 4);                              \
        aR[2] = *(const float4*)(_ap + 8);                              \
        aR[3] = *(const float4*)(_ap + 12);                             \
        const float* _bp = Bbase + (c) * 32;                            \
        bR[0] = *(const float4*)(_bp + 0);                              \
        bR[1] = *(const float4*)(_bp + 4);                              \
    } while (0)

#define STORES(buf) do {                                                \
        int _mf = arow >> 4, _r = arow & 15;                            \
        int _ael = (_r >> 3);                                           \
        int _aln = (_r & 7) * 4;                                        \
        _Pragma("unroll")                                               \
        for (int v = 0; v < 4; v++) {                                   \
            float _vals[4] = {aR[v].x, aR[v].y, aR[v].z, aR[v].w};      \
            _Pragma("unroll")                                           \
            for (int j = 0; j < 4; j++) {                               \
                int kk = akb + v * 4 + j;                               \
                int ks = kk >> 3, kc = kk & 7;                          \
                uint32_t hi, lo;                                        \
                split_tf32(_vals[j], hi, lo);                           \
                uint32_t base = (((((buf) * 4 + ks) * 8 + _mf) * 2) * 32 \
                                 + _aln + (kc & 3)) * 4                 \
                                + _ael + 2 * (kc >> 2);                 \
                sA[base] = hi;                                          \
                sA[base + 128] = lo;                                    \
            }                                                           \
        }                                                               \
        int _nf = brow >> 3, _nn = brow & 7;                            \
        _Pragma("unroll")                                               \
        for (int v = 0; v < 2; v++) {                                   \
            float _vals[4] = {bR[v].x, bR[v].y, bR[v].z, bR[v].w};      \
            _Pragma("unroll")                                           \
            for (int j = 0; j < 4; j++) {                               \
                int kk = bkb + v * 4 + j;                               \
                int ks = kk >> 3, kc = kk & 7;                          \
                uint32_t hi, lo;                                        \
                split_tf32(_vals[j], hi, lo);                           \
                uint32_t base = (((((buf) * 4 + ks) * 8 + _nf) * 2) * 32 \
                                 + _nn * 4 + (kc & 3)) * 2              \
                                + (kc >> 2);                            \
                sB[base] = hi;                                          \
                sB[base + 64] = lo;                                     \
            }                                                           \
        }                                                               \
    } while (0)

    int nch = K >> 5;
    LOADG(0);
    STORES(0);
    __syncthreads();

    for (int c = 0; c < nch; c++) {
        int buf = c & 1;
        if (c + 1 < nch) LOADG(c + 1);
#pragma unroll
        for (int ks = 0; ks < 4; ks++) {
            uint4 Ah[2], Al[2];
#pragma unroll
            for (int i = 0; i < 2; i++) {
                uint32_t off = ((((buf * 4 + ks) * 8 + (wm * 2 + i)) * 2) * 32
                                + lane) * 4;
                Ah[i] = *(const uint4*)(sA + off);
                Al[i] = *(const uint4*)(sA + off + 128);
            }
            uint2 Bh[4], Bl[4];
#pragma unroll
            for (int j = 0; j < 4; j++) {
                uint32_t off = ((((buf * 4 + ks) * 8 + (wn * 4 + j)) * 2) * 32
                                + lane) * 2;
                Bh[j] = *(const uint2*)(sB + off);
                Bl[j] = *(const uint2*)(sB + off + 64);
            }
#pragma unroll
            for (int i = 0; i < 2; i++)
#pragma unroll
                for (int j = 0; j < 4; j++) {
                    mma8(acc[i][j], Ah[i], Bh[j]);
                    mma8(acc[i][j], Ah[i], Bl[j]);
                    mma8(acc[i][j], Al[i], Bh[j]);
                }
        }
        if (c + 1 < nch) {
            STORES((c + 1) & 1);
            __syncthreads();
        }
    }

    // Epilogue: direct fp32 stores (float2, 32B-sector aligned groups).
#pragma unroll
    for (int i = 0; i < 2; i++)
#pragma unroll
        for (int j = 0; j < 4; j++) {
            int rg = m0 + wm * 32 + i * 16 + (lane >> 2);
            int cg = n0 + wn * 32 + j * 8 + (lane & 3) * 2;
            float d0 = acc[i][j][0], d1 = acc[i][j][1];
            float d2 = acc[i][j][2], d3 = acc[i][j][3];
            if (mode >= 1) {
                float b0 = bias[cg], b1 = bias[cg + 1];
                d0 += b0; d1 += b1; d2 += b0; d3 += b1;
            }
            if (mode == 2) {
                d0 = gelu_f(d0); d1 = gelu_f(d1);
                d2 = gelu_f(d2); d3 = gelu_f(d3);
            }
            float2 w0 = {d0, d1}, w1 = {d2, d3};
            *(float2*)(Co + (size_t)rg * Nn + cg) = w0;
            *(float2*)(Co + (size_t)(rg + 8) * Nn + cg) = w1;
        }
}

__global__ __launch_bounds__(256, 2)
void gemm_kv(const float* __restrict__ w) {
    gemm_body(g_xn, w, nullptr, g_kv, B_ * N_, 2 * C_, C_, 0);
}
__global__ __launch_bounds__(256, 2)
void gemm_fc1(const float* __restrict__ w, const float* __restrict__ b) {
    gemm_body(g_qc1, w, b, g_hb, B_ * NT_, 2 * C_, C_, 2);
}
__global__ __launch_bounds__(256, 2)
void gemm_fc2(const float* __restrict__ w, const float* __restrict__ b) {
    gemm_body(g_hb, w, b, g_qc2, B_ * NT_, C_, 2 * C_, 1);
}
__global__ __launch_bounds__(256, 2)
void gemm_proj(const float* __restrict__ w, const float* __restrict__ b,
               float* __restrict__ out) {
    gemm_body(g_av, w, b, out, B_ * NT_, C_, C_, 1);
}

// ---------------------------------------------------------------------------
// K0: LayerNorm -> g_xn (fp32). One block per row, 128 threads.
// ---------------------------------------------------------------------------
__global__ void ln_kernel(const float* __restrict__ x,
                          const float* __restrict__ w,
                          const float* __restrict__ b) {
    int row = blockIdx.x;
    const float* xr = x + (size_t)row * C_;
    int tid = threadIdx.x;
    float v[3];
    float s = 0.f, sq = 0.f;
#pragma unroll
    for (int i = 0; i < 3; i++) {
        v[i] = xr[tid + 128 * i];
        s += v[i]; sq += v[i] * v[i];
    }
#pragma unroll
    for (int o = 16; o; o >>= 1) {
        s  += __shfl_xor_sync(0xffffffffu, s, o);
        sq += __shfl_xor_sync(0xffffffffu, sq, o);
    }
    __shared__ float ss[4], ssq[4];
    if ((tid & 31) == 0) { ss[tid >> 5] = s; ssq[tid >> 5] = sq; }
    __syncthreads();
    s  = ss[0] + ss[1] + ss[2] + ss[3];
    sq = ssq[0] + ssq[1] + ssq[2] + ssq[3];
    float mu = s * (1.0f / C_);
    float var = sq * (1.0f / C_) - mu * mu;
    float rstd = rsqrtf(var + EPS_);
    float* orow = g_xn + (size_t)row * C_;
#pragma unroll
    for (int i = 0; i < 3; i++) {
        int c = tid + 128 * i;
        orow[c] = (v[i] - mu) * rstd * w[c] + b[c];
    }
}

// ---------------------------------------------------------------------------
// K2: attn1 + q_cond1 -> g_qc1 (fp32). One block per (b,h).
// ---------------------------------------------------------------------------
#define ATTN1_SMEM (3 * NT_ * HD_ * 4)

__global__ __launch_bounds__(256)
void attn1_kernel(const float* __restrict__ qg, const int* __restrict__ idx_sub) {
    extern __shared__ float sh[];
    float* qs = sh;
    float* ks = sh + NT_ * HD_;
    float* vs = sh + 2 * NT_ * HD_;
    int b = blockIdx.x >> 3;
    int h = blockIdx.x & 7;
    int tid = threadIdx.x;

    for (int i = tid; i < NT_ * HD_; i += 256) {
        int n = i / HD_, d = i % HD_;
        qs[i] = qg[((size_t)n * H_ + h) * HD_ + d];
        int src = idx_sub[n];
        const float* kvrow = g_kv + ((size_t)b * N_ + src) * (2 * C_) + h * HD_ + d;
        ks[i] = kvrow[0];
        vs[i] = kvrow[C_];
    }
    __syncthreads();

    int m = tid;
    if (m < NT_) {
        float sc[NT_];
        float mx = -1e30f;
        const float* qm = qs + m * HD_;
        for (int n = 0; n < NT_; n++) {
            const float* kn = ks + n * HD_;
            float s = 0.f;
#pragma unroll
            for (int d = 0; d < HD_; d++) s += qm[d] * kn[d];
            s *= SCALE_;
            sc[n] = s;
            mx = fmaxf(mx, s);
        }
        float sum = 0.f;
        for (int n = 0; n < NT_; n++) {
            float e = expf(sc[n] - mx);
            sc[n] = e; sum += e;
        }
        float inv = 1.0f / sum;
        float accv[HD_];
#pragma unroll
        for (int d = 0; d < HD_; d++) accv[d] = 0.f;
        for (int n = 0; n < NT_; n++) {
            float wgt = sc[n];
            const float* vn = vs + n * HD_;
#pragma unroll
            for (int d = 0; d < HD_; d++) accv[d] += wgt * vn[d];
        }
        float* orow = g_qc1 + ((size_t)b * NT_ + m) * C_ + h * HD_;
#pragma unroll
        for (int d = 0; d < HD_; d++) orow[d] = accv[d] * inv;
    }
}

// ---------------------------------------------------------------------------
// K5: attn2 mean-over-heads + argmax (fp32-exact; first-index tie rule).
// ---------------------------------------------------------------------------
#define MCH 7
__global__ __launch_bounds__(256)
void attn2_kernel(const int* __restrict__ idxs) {
    int b = blockIdx.x / 28;
    int m0 = (blockIdx.x % 28) * MCH;
    __shared__ float qsh[MCH * C_];
    __shared__ float krow[C_];
    __shared__ int sIdxs[NT_];
    int tid = threadIdx.x;
    for (int i = tid; i < MCH * C_; i += 256)
        qsh[i] = g_qc2[((size_t)b * NT_ + m0) * C_ + i];
    for (int i = tid; i < NT_; i += 256) sIdxs[i] = idxs[i];
    int warp = tid >> 5, lane = tid & 31;
    float best = -1e30f;
    int bestn = 0;
    __syncthreads();
    for (int n = 0; n < NT_; n++) {
        __syncthreads();
        for (int i = tid; i < C_; i += 256)
            krow[i] = g_kv[((size_t)b * N_ + sIdxs[n]) * (2 * C_) + i];
        __syncthreads();
        if (warp < MCH) {
            const float* qm = qsh + warp * C_;
            float p = 0.f;
#pragma unroll
            for (int j = 0; j < 12; j++) p += qm[lane + 32 * j] * krow[lane + 32 * j];
#pragma unroll
            for (int o = 16; o; o >>= 1) p += __shfl_xor_sync(0xffffffffu, p, o);
            if (p > best) { best = p; bestn = n; }
        }
    }
    if (warp < MCH && lane == 0)
        g_cent[(size_t)b * NT_ + m0 + warp] = sIdxs[bestn];
}

// ---------------------------------------------------------------------------
// K6: masked attn3 (sparse over deduped adjusted-index set) -> g_av.
// ---------------------------------------------------------------------------
__global__ __launch_bounds__(256)
void attn3_kernel() {
    int bm = blockIdx.x;
    int b = bm / NT_;
    __shared__ unsigned int bmap[N_ / 32];
    __shared__ int sIdx[169];
    __shared__ int cnt;
    __shared__ float sQ[C_];
    __shared__ float sS[H_][169];
    int tid = threadIdx.x;
    if (tid < N_ / 32) bmap[tid] = 0u;
    if (tid == 0) cnt = 0;
    __syncthreads();
    int ci = g_cent[bm];
    if (tid < 169) {
        int row = tid / 13 - 6;
        int col = tid % 13 - 6;
        int adj = ci + (col - 56 * row);
        adj = max(0, min(N_ - 1, adj));
        atomicOr(&bmap[adj >> 5], 1u << (adj & 31));
    }
    for (int i = tid; i < C_; i += 256)
        sQ[i] = g_qc2[(size_t)bm * C_ + i] * SCALE_;
    __syncthreads();
    if (tid < N_ / 32) {
        unsigned int w = bmap[tid];
        if (w) {
            int base = atomicAdd(&cnt, __popc(w));
            int off = 0;
            while (w) {
                int bit = __ffs(w) - 1;
                w &= w - 1;
                sIdx[base + off] = (tid << 5) + bit;
                off++;
            }
        }
    }
    __syncthreads();
    int count = cnt;
    int h = tid >> 5, lane = tid & 31;
    const float* qh = sQ + h * HD_;
    float mx = -1e30f;
    for (int e = 0; e < count; e++) {
        const float* kr = g_kv + ((size_t)b * N_ + sIdx[e]) * (2 * C_) + h * HD_;
        float p = kr[lane] * qh[lane];
        if (lane < 16) p += kr[lane + 32] * qh[lane + 32];
#pragma unroll
        for (int o = 16; o; o >>= 1) p += __shfl_xor_sync(0xffffffffu, p, o);
        if (lane == 0) sS[h][e] = p;
        mx = fmaxf(mx, p);
    }
    __syncwarp();
    float sum = 0.f;
    for (int e = lane; e < count; e += 32) {
        float ee = expf(sS[h][e] - mx);
        sS[h][e] = ee;
        sum += ee;
    }
#pragma unroll
    for (int o = 16; o; o >>= 1) sum += __shfl_xor_sync(0xffffffffu, sum, o);
    float inv = 1.0f / sum;
    __syncwarp();
    float a0 = 0.f, a1 = 0.f;
    for (int e = 0; e < count; e++) {
        float wgt = sS[h][e];
        const float* vr = g_kv + ((size_t)b * N_ + sIdx[e]) * (2 * C_) + C_ + h * HD_;
        a0 += wgt * vr[lane];
        if (lane < 16) a1 += wgt * vr[lane + 32];
    }
    float* orow = g_av + (size_t)bm * C_ + h * HD_;
    orow[lane] = a0 * inv;
    if (lane < 16) orow[lane + 32] = a1 * inv;
}

// ---------------------------------------------------------------------------
// Launch: kernel launches only.
// ---------------------------------------------------------------------------
extern "C" void kernel_launch(void* const* d_in, const int* in_sizes, int n_in,
                              void* d_out, int out_size) {
    const float* x      = (const float*)d_in[0];
    const float* q      = (const float*)d_in[1];
    const float* kv_w   = (const float*)d_in[2];
    const float* proj_w = (const float*)d_in[3];
    const float* proj_b = (const float*)d_in[4];
    const float* ln_w   = (const float*)d_in[5];
    const float* ln_b   = (const float*)d_in[6];
    const float* fc1_w  = (const float*)d_in[7];
    const float* fc1_b  = (const float*)d_in[8];
    const float* fc2_w  = (const float*)d_in[9];
    const float* fc2_b  = (const float*)d_in[10];
    const int* idx_sub  = (const int*)d_in[11];
    const int* idxs     = (const int*)d_in[12];
    float* out = (float*)d_out;

    cudaFuncSetAttribute(attn1_kernel,
                         cudaFuncAttributeMaxDynamicSharedMemorySize, ATTN1_SMEM);
    cudaFuncSetAttribute(gemm_kv,
                         cudaFuncAttributeMaxDynamicSharedMemorySize, GEMM_SMEM);
    cudaFuncSetAttribute(gemm_fc1,
                         cudaFuncAttributeMaxDynamicSharedMemorySize, GEMM_SMEM);
    cudaFuncSetAttribute(gemm_fc2,
                         cudaFuncAttributeMaxDynamicSharedMemorySize, GEMM_SMEM);
    cudaFuncSetAttribute(gemm_proj,
                         cudaFuncAttributeMaxDynamicSharedMemorySize, GEMM_SMEM);

    // K0: LayerNorm -> g_xn
    ln_kernel<<<B_ * N_, 128>>>(x, ln_w, ln_b);

    // K1: KV projection (3xTF32 mma.sync) -> g_kv
    gemm_kv<<<dim3(2 * C_ / 64, (B_ * N_) / 128), 256, GEMM_SMEM>>>(kv_w);

    // K2: attn1 -> g_qc1
    attn1_kernel<<<B_ * H_, 256, ATTN1_SMEM>>>(q, idx_sub);

    // K3: fc1 + gelu -> g_hb
    gemm_fc1<<<dim3(2 * C_ / 64, (B_ * NT_) / 128), 256, GEMM_SMEM>>>(fc1_w, fc1_b);

    // K4: fc2 -> g_qc2
    gemm_fc2<<<dim3(C_ / 64, (B_ * NT_) / 128), 256, GEMM_SMEM>>>(fc2_w, fc2_b);

    // K5: attn2 + argmax -> g_cent
    attn2_kernel<<<B_ * 28, 256>>>(idxs);

    // K6: sparse masked attn3 -> g_av
    attn3_kernel<<<B_ * NT_, 256>>>();

    // K7: output projection -> d_out
    gemm_proj<<<dim3(C_ / 64, (B_ * NT_) / 128), 256, GEMM_SMEM>>>(proj_b ? proj_w : proj_w, proj_b, out);
}

// round 11
// speedup vs baseline: 1.2882x; 1.2882x over previous
#include <cuda_runtime.h>
#include <cstdint>
#include <math.h>

#define B_   32
#define N_   3136
#define C_   384
#define H_   8
#define HD_  48
#define NT_  196
#define EPS_ 1e-6f
#define SCALE_ 0.14433756729740643f   /* 1/sqrt(48) */

typedef unsigned long long ull;

// ---------------------------------------------------------------------------
// Scratch: one big static device buffer (no runtime allocation).
// Identical layout to the R3 kernel that passed at 2559us.
// ---------------------------------------------------------------------------
#define XN_OFF   ((size_t)0)
#define KV_OFF   (XN_OFF  + (size_t)B_*N_*C_)
#define QC1_OFF  (KV_OFF  + (size_t)B_*N_*2*C_)
#define HB_OFF   (QC1_OFF + (size_t)B_*NT_*C_)
#define QC2_OFF  (HB_OFF  + (size_t)B_*NT_*2*C_)
#define AV_OFF   (QC2_OFF + (size_t)B_*NT_*C_)
#define CENT_OFF (AV_OFF  + (size_t)B_*NT_*C_)
#define TOTAL_F  (CENT_OFF + (size_t)B_*NT_)

__device__ __align__(128) float g_scratch[TOTAL_F];

#define G_XN   (g_scratch + XN_OFF)
#define G_KV   (g_scratch + KV_OFF)
#define G_QC1  (g_scratch + QC1_OFF)
#define G_HB   (g_scratch + HB_OFF)
#define G_QC2  (g_scratch + QC2_OFF)
#define G_AV   (g_scratch + AV_OFF)
#define G_CENT ((int*)(g_scratch + CENT_OFF))

// ---------------------------------------------------------------------------
// f32x2 packed helpers
// ---------------------------------------------------------------------------
__device__ __forceinline__ ull pack2(float x, float y) {
    ull r; asm("mov.b64 %0, {%1,%2};" : "=l"(r) : "f"(x), "f"(y)); return r;
}
__device__ __forceinline__ float2 unpack2(ull v) {
    float2 f; asm("mov.b64 {%0,%1}, %2;" : "=f"(f.x), "=f"(f.y) : "l"(v)); return f;
}
__device__ __forceinline__ void fma2(ull& d, ull a, ull b) {
    asm("fma.rn.f32x2 %0, %1, %2, %0;" : "+l"(d) : "l"(a), "l"(b));
}

__device__ __forceinline__ float gelu_f(float x) {
    return 0.5f * x * (1.0f + erff(x * 0.70710678118654752f));
}

// ---------------------------------------------------------------------------
// K0: LayerNorm. One block per row, 128 threads, 3 elems/thread.
// ---------------------------------------------------------------------------
__global__ void ln_kernel(const float* __restrict__ x,
                          const float* __restrict__ w,
                          const float* __restrict__ b) {
    int row = blockIdx.x;
    const float* xr = x + (size_t)row * C_;
    int tid = threadIdx.x;
    float v[3];
    float s = 0.f, sq = 0.f;
#pragma unroll
    for (int i = 0; i < 3; i++) {
        v[i] = xr[tid + 128 * i];
        s += v[i]; sq += v[i] * v[i];
    }
#pragma unroll
    for (int o = 16; o; o >>= 1) {
        s  += __shfl_xor_sync(0xffffffffu, s, o);
        sq += __shfl_xor_sync(0xffffffffu, sq, o);
    }
    __shared__ float ss[4], ssq[4];
    if ((tid & 31) == 0) { ss[tid >> 5] = s; ssq[tid >> 5] = sq; }
    __syncthreads();
    s  = ss[0] + ss[1] + ss[2] + ss[3];
    sq = ssq[0] + ssq[1] + ssq[2] + ssq[3];
    float mu = s * (1.0f / C_);
    float var = sq * (1.0f / C_) - mu * mu;
    float rstd = rsqrtf(var + EPS_);
    float* orow = G_XN + (size_t)row * C_;
#pragma unroll
    for (int i = 0; i < 3; i++) {
        int c = tid + 128 * i;
        orow[c] = (v[i] - mu) * rstd * w[c] + b[c];
    }
}

// ---------------------------------------------------------------------------
// GEMM: C[M,Nn] = A[M,K] @ W[Nn,K]^T (+bias)(+gelu)
// 128x128x16 tile, 256 threads, 8x8 microtile, f32x2 math,
// register-staged double-buffered smem (one barrier per BK).
// (Byte-identical to the R3 GEMM that passed.)
// ---------------------------------------------------------------------------
#define BM 128
#define BN 128
#define BK 16

__device__ __forceinline__
void gemm_body(const float* __restrict__ A, const float* __restrict__ W,
               const float* __restrict__ bias, float* __restrict__ Cm,
               int M, int Nn, int K, int epi) {
    __shared__ __align__(16) float As[2][BK][BM];
    __shared__ __align__(16) float Bs[2][BK][BN];
    int tid = threadIdx.x;
    int tx = tid & 15, ty = tid >> 4;
    int m0 = blockIdx.y * BM, n0 = blockIdx.x * BN;

    int lr = tid >> 1;
    int lc = (tid & 1) * 8;
    const float* Aptr = A + (size_t)(m0 + lr) * K + lc;
    const float* Wptr = W + (size_t)(n0 + lr) * K + lc;

    ull acc[8][4];
#pragma unroll
    for (int i = 0; i < 8; i++)
#pragma unroll
        for (int j = 0; j < 4; j++) acc[i][j] = 0ull;

    float4 a0 = *(const float4*)(Aptr + 0);
    float4 a1 = *(const float4*)(Aptr + 4);
    float4 b0 = *(const float4*)(Wptr + 0);
    float4 b1 = *(const float4*)(Wptr + 4);
    As[0][lc + 0][lr] = a0.x; As[0][lc + 1][lr] = a0.y;
    As[0][lc + 2][lr] = a0.z; As[0][lc + 3][lr] = a0.w;
    As[0][lc + 4][lr] = a1.x; As[0][lc + 5][lr] = a1.y;
    As[0][lc + 6][lr] = a1.z; As[0][lc + 7][lr] = a1.w;
    Bs[0][lc + 0][lr] = b0.x; Bs[0][lc + 1][lr] = b0.y;
    Bs[0][lc + 2][lr] = b0.z; Bs[0][lc + 3][lr] = b0.w;
    Bs[0][lc + 4][lr] = b1.x; Bs[0][lc + 5][lr] = b1.y;
    Bs[0][lc + 6][lr] = b1.z; Bs[0][lc + 7][lr] = b1.w;
    __syncthreads();

    int nk = K / BK;
    for (int kt = 0; kt < nk; kt++) {
        int cur = kt & 1;
        if (kt + 1 < nk) {
            const float* Ap = Aptr + (kt + 1) * BK;
            const float* Wp = Wptr + (kt + 1) * BK;
            a0 = *(const float4*)(Ap + 0);
            a1 = *(const float4*)(Ap + 4);
            b0 = *(const float4*)(Wp + 0);
            b1 = *(const float4*)(Wp + 4);
        }
#pragma unroll
        for (int kk = 0; kk < BK; kk++) {
            float4 av0 = *(const float4*)&As[cur][kk][ty * 8];
            float4 av1 = *(const float4*)&As[cur][kk][ty * 8 + 4];
            float4 bv0 = *(const float4*)&Bs[cur][kk][tx * 8];
            float4 bv1 = *(const float4*)&Bs[cur][kk][tx * 8 + 4];
            ull bp0 = pack2(bv0.x, bv0.y);
            ull bp1 = pack2(bv0.z, bv0.w);
            ull bp2 = pack2(bv1.x, bv1.y);
            ull bp3 = pack2(bv1.z, bv1.w);
            float am[8] = {av0.x, av0.y, av0.z, av0.w,
                           av1.x, av1.y, av1.z, av1.w};
#pragma unroll
            for (int i = 0; i < 8; i++) {
                ull ap = pack2(am[i], am[i]);
                fma2(acc[i][0], ap, bp0);
                fma2(acc[i][1], ap, bp1);
                fma2(acc[i][2], ap, bp2);
                fma2(acc[i][3], ap, bp3);
            }
        }
        if (kt + 1 < nk) {
            int nxt = 1 - cur;
            As[nxt][lc + 0][lr] = a0.x; As[nxt][lc + 1][lr] = a0.y;
            As[nxt][lc + 2][lr] = a0.z; As[nxt][lc + 3][lr] = a0.w;
            As[nxt][lc + 4][lr] = a1.x; As[nxt][lc + 5][lr] = a1.y;
            As[nxt][lc + 6][lr] = a1.z; As[nxt][lc + 7][lr] = a1.w;
            Bs[nxt][lc + 0][lr] = b0.x; Bs[nxt][lc + 1][lr] = b0.y;
            Bs[nxt][lc + 2][lr] = b0.z; Bs[nxt][lc + 3][lr] = b0.w;
            Bs[nxt][lc + 4][lr] = b1.x; Bs[nxt][lc + 5][lr] = b1.y;
            Bs[nxt][lc + 6][lr] = b1.z; Bs[nxt][lc + 7][lr] = b1.w;
            __syncthreads();
        }
    }

    int gn = n0 + tx * 8;
    float bb[8];
#pragma unroll
    for (int j = 0; j < 8; j++) bb[j] = bias ? bias[gn + j] : 0.f;
#pragma unroll
    for (int i = 0; i < 8; i++) {
        int gm = m0 + ty * 8 + i;
        float o[8];
#pragma unroll
        for (int j = 0; j < 4; j++) {
            float2 c = unpack2(acc[i][j]);
            o[2 * j] = c.x + bb[2 * j];
            o[2 * j + 1] = c.y + bb[2 * j + 1];
        }
        if (epi == 1) {
#pragma unroll
            for (int j = 0; j < 8; j++) o[j] = gelu_f(o[j]);
        }
        float4 w0 = {o[0], o[1], o[2], o[3]};
        float4 w1 = {o[4], o[5], o[6], o[7]};
        *(float4*)(Cm + (size_t)gm * Nn + gn) = w0;
        *(float4*)(Cm + (size_t)gm * Nn + gn + 4) = w1;
    }
}

__global__ __launch_bounds__(256, 2) void gemm_xn_kv(const float* __restrict__ kv_w) {
    gemm_body(G_XN, kv_w, nullptr, G_KV, B_ * N_, 2 * C_, C_, 0);
}
__global__ __launch_bounds__(256, 2) void gemm_qc1_hb(const float* __restrict__ w,
                                                      const float* __restrict__ b) {
    gemm_body(G_QC1, w, b, G_HB, B_ * NT_, 2 * C_, C_, 1);
}
__global__ __launch_bounds__(256, 2) void gemm_hb_qc2(const float* __restrict__ w,
                                                      const float* __restrict__ b) {
    gemm_body(G_HB, w, b, G_QC2, B_ * NT_, C_, 2 * C_, 0);
}
__global__ __launch_bounds__(256, 2) void gemm_av_out(const float* __restrict__ w,
                                                      const float* __restrict__ b,
                                                      float* __restrict__ out) {
    gemm_body(G_AV, w, b, out, B_ * NT_, C_, C_, 0);
}

// ---------------------------------------------------------------------------
// K2: attn1 + q_cond1. One block per (b,h). (R3-identical.)
// ---------------------------------------------------------------------------
#define ATTN1_SMEM (3 * NT_ * HD_ * 4)

__global__ __launch_bounds__(256)
void attn1_kernel(const float* __restrict__ qg, const int* __restrict__ idx_sub) {
    extern __shared__ float sh[];
    float* qs = sh;
    float* ks = sh + NT_ * HD_;
    float* vs = sh + 2 * NT_ * HD_;
    int b = blockIdx.x >> 3;
    int h = blockIdx.x & 7;
    int tid = threadIdx.x;

    for (int i = tid; i < NT_ * HD_; i += 256) {
        int n = i / HD_, d = i % HD_;
        qs[i] = qg[((size_t)n * H_ + h) * HD_ + d];
        int src = idx_sub[n];
        const float* kvrow = G_KV + ((size_t)b * N_ + src) * (2 * C_) + h * HD_ + d;
        ks[i] = kvrow[0];
        vs[i] = kvrow[C_];
    }
    __syncthreads();

    int m = tid;
    if (m < NT_) {
        float sc[NT_];
        float mx = -1e30f;
        const float* qm = qs + m * HD_;
        for (int n = 0; n < NT_; n++) {
            const float* kn = ks + n * HD_;
            float s = 0.f;
#pragma unroll
            for (int d = 0; d < HD_; d++) s += qm[d] * kn[d];
            s *= SCALE_;
            sc[n] = s;
            mx = fmaxf(mx, s);
        }
        float sum = 0.f;
        for (int n = 0; n < NT_; n++) {
            float e = expf(sc[n] - mx);
            sc[n] = e; sum += e;
        }
        float inv = 1.0f / sum;
        float accv[HD_];
#pragma unroll
        for (int d = 0; d < HD_; d++) accv[d] = 0.f;
        for (int n = 0; n < NT_; n++) {
            float wgt = sc[n];
            const float* vn = vs + n * HD_;
#pragma unroll
            for (int d = 0; d < HD_; d++) accv[d] += wgt * vn[d];
        }
        float* orow = G_QC1 + ((size_t)b * NT_ + m) * C_ + h * HD_;
#pragma unroll
        for (int d = 0; d < HD_; d++) orow[d] = accv[d] * inv;
    }
}

// ---------------------------------------------------------------------------
// K5: attn2 mean-over-heads + argmax. TILED: 8 k-rows per barrier pair
// (R3 did 1 row / 2 barriers = 392 barriers; now ~50). Dot order and the
// strict-> ascending-n first-index tie rule are unchanged.
// ---------------------------------------------------------------------------
#define MCH 7
#define KT  8
__global__ __launch_bounds__(256)
void attn2_kernel(const int* __restrict__ idxs) {
    int b = blockIdx.x / 28;
    int m0 = (blockIdx.x % 28) * MCH;
    __shared__ float qsh[MCH * C_];
    __shared__ float krows[KT][C_];
    __shared__ int sIdxs[NT_];
    int tid = threadIdx.x;
    for (int i = tid; i < MCH * C_; i += 256)
        qsh[i] = G_QC2[((size_t)b * NT_ + m0) * C_ + i];
    for (int i = tid; i < NT_; i += 256) sIdxs[i] = idxs[i];
    int warp = tid >> 5, lane = tid & 31;
    float best = -1e30f;
    int bestn = 0;
    __syncthreads();
    for (int t0 = 0; t0 < NT_; t0 += KT) {
        int nrows = min(KT, NT_ - t0);
        __syncthreads();
        for (int i = tid; i < nrows * C_; i += 256) {
            int r = i / C_, c = i % C_;
            krows[r][c] = G_KV[((size_t)b * N_ + sIdxs[t0 + r]) * (2 * C_) + c];
        }
        __syncthreads();
        if (warp < MCH) {
            const float* qm = qsh + warp * C_;
            for (int r = 0; r < nrows; r++) {
                float p = 0.f;
#pragma unroll
                for (int j = 0; j < 12; j++)
                    p += qm[lane + 32 * j] * krows[r][lane + 32 * j];
#pragma unroll
                for (int o = 16; o; o >>= 1) p += __shfl_xor_sync(0xffffffffu, p, o);
                if (p > best) { best = p; bestn = t0 + r; }
            }
        }
    }
    if (warp < MCH && lane == 0)
        G_CENT[(size_t)b * NT_ + m0 + warp] = sIdxs[bestn];
}

// ---------------------------------------------------------------------------
// K6: masked attn3 (sparse over deduped adjusted-index set). (R3-identical.)
// ---------------------------------------------------------------------------
__global__ __launch_bounds__(256)
void attn3_kernel() {
    int bm = blockIdx.x;
    int b = bm / NT_;
    __shared__ unsigned int bmap[N_ / 32];
    __shared__ int sIdx[169];
    __shared__ int cnt;
    __shared__ float sQ[C_];
    __shared__ float sS[H_][169];
    int tid = threadIdx.x;
    if (tid < N_ / 32) bmap[tid] = 0u;
    if (tid == 0) cnt = 0;
    __syncthreads();
    int ci = G_CENT[bm];
    if (tid < 169) {
        int row = tid / 13 - 6;
        int col = tid % 13 - 6;
        int adj = ci + (col - 56 * row);
        adj = max(0, min(N_ - 1, adj));
        atomicOr(&bmap[adj >> 5], 1u << (adj & 31));
    }
    for (int i = tid; i < C_; i += 256)
        sQ[i] = G_QC2[(size_t)bm * C_ + i] * SCALE_;
    __syncthreads();
    if (tid < N_ / 32) {
        unsigned int w = bmap[tid];
        if (w) {
            int base = atomicAdd(&cnt, __popc(w));
            int off = 0;
            while (w) {
                int bit = __ffs(w) - 1;
                w &= w - 1;
                sIdx[base + off] = (tid << 5) + bit;
                off++;
            }
        }
    }
    __syncthreads();
    int count = cnt;
    int h = tid >> 5, lane = tid & 31;
    const float* qh = sQ + h * HD_;
    float mx = -1e30f;
    for (int e = 0; e < count; e++) {
        const float* kr = G_KV + ((size_t)b * N_ + sIdx[e]) * (2 * C_) + h * HD_;
        float p = kr[lane] * qh[lane];
        if (lane < 16) p += kr[lane + 32] * qh[lane + 32];
#pragma unroll
        for (int o = 16; o; o >>= 1) p += __shfl_xor_sync(0xffffffffu, p, o);
        if (lane == 0) sS[h][e] = p;
        mx = fmaxf(mx, p);
    }
    __syncwarp();
    float sum = 0.f;
    for (int e = lane; e < count; e += 32) {
        float ee = expf(sS[h][e] - mx);
        sS[h][e] = ee;
        sum += ee;
    }
#pragma unroll
    for (int o = 16; o; o >>= 1) sum += __shfl_xor_sync(0xffffffffu, sum, o);
    float inv = 1.0f / sum;
    __syncwarp();
    float a0 = 0.f, a1 = 0.f;
    for (int e = 0; e < count; e++) {
        float wgt = sS[h][e];
        const float* vr = G_KV + ((size_t)b * N_ + sIdx[e]) * (2 * C_) + C_ + h * HD_;
        a0 += wgt * vr[lane];
        if (lane < 16) a1 += wgt * vr[lane + 32];
    }
    float* orow = G_AV + (size_t)bm * C_ + h * HD_;
    orow[lane] = a0 * inv;
    if (lane < 16) orow[lane + 32] = a1 * inv;
}

// ---------------------------------------------------------------------------
// Launch: kernel launches only.
// ---------------------------------------------------------------------------
extern "C" void kernel_launch(void* const* d_in, const int* in_sizes, int n_in,
                              void* d_out, int out_size) {
    const float* x      = (const float*)d_in[0];
    const float* q      = (const float*)d_in[1];
    const float* kv_w   = (const float*)d_in[2];
    const float* proj_w = (const float*)d_in[3];
    const float* proj_b = (const float*)d_in[4];
    const float* ln_w   = (const float*)d_in[5];
    const float* ln_b   = (const float*)d_in[6];
    const float* fc1_w  = (const float*)d_in[7];
    const float* fc1_b  = (const float*)d_in[8];
    const float* fc2_w  = (const float*)d_in[9];
    const float* fc2_b  = (const float*)d_in[10];
    const int* idx_sub  = (const int*)d_in[11];
    const int* idxs     = (const int*)d_in[12];
    float* out = (float*)d_out;

    cudaFuncSetAttribute(attn1_kernel,
                         cudaFuncAttributeMaxDynamicSharedMemorySize, ATTN1_SMEM);

    // K0: LayerNorm -> G_XN
    ln_kernel<<<B_ * N_, 128>>>(x, ln_w, ln_b);

    // K1: KV projection (dominant GEMM, fp32-exact)
    {
        dim3 g(2 * C_ / BN, (B_ * N_) / BM);
        gemm_xn_kv<<<g, 256>>>(kv_w);
    }

    // K2: attn1 -> G_QC1
    attn1_kernel<<<B_ * H_, 256, ATTN1_SMEM>>>(q, idx_sub);

    // K3: fc1 + gelu -> G_HB
    {
        dim3 g(2 * C_ / BN, (B_ * NT_) / BM);
        gemm_qc1_hb<<<g, 256>>>(fc1_w, fc1_b);
    }
    // K4: fc2 -> G_QC2
    {
        dim3 g(C_ / BN, (B_ * NT_) / BM);
        gemm_hb_qc2<<<g, 256>>>(fc2_w, fc2_b);
    }

    // K5: attn2 + argmax -> G_CENT
    attn2_kernel<<<B_ * 28, 256>>>(idxs);

    // K6: sparse masked attn3 -> G_AV
    attn3_kernel<<<B_ * NT_, 256>>>();

    // K7: output projection -> d_out
    {
        dim3 g(C_ / BN, (B_ * NT_) / BM);
        gemm_av_out<<<g, 256>>>(proj_w, proj_b, out);
    }
}

// round 12
// speedup vs baseline: 1.3188x; 1.0238x over previous
#include <cuda_runtime.h>
#include <cstdint>
#include <math.h>

#define B_   32
#define N_   3136
#define C_   384
#define H_   8
#define HD_  48
#define NT_  196
#define EPS_ 1e-6f
#define SCALE_ 0.14433756729740643f   /* 1/sqrt(48) */

typedef unsigned long long ull;

// ---------------------------------------------------------------------------
// Scratch: one big static device buffer (no runtime allocation).
// ---------------------------------------------------------------------------
#define XN_OFF   ((size_t)0)
#define KV_OFF   (XN_OFF  + (size_t)B_*N_*C_)
#define QC1_OFF  (KV_OFF  + (size_t)B_*N_*2*C_)
#define HB_OFF   (QC1_OFF + (size_t)B_*NT_*C_)
#define QC2_OFF  (HB_OFF  + (size_t)B_*NT_*2*C_)
#define AV_OFF   (QC2_OFF + (size_t)B_*NT_*C_)
#define CENT_OFF (AV_OFF  + (size_t)B_*NT_*C_)
#define TOTAL_F  (CENT_OFF + (size_t)B_*NT_)

__device__ __align__(128) float g_scratch[TOTAL_F];

#define G_XN   (g_scratch + XN_OFF)
#define G_KV   (g_scratch + KV_OFF)
#define G_QC1  (g_scratch + QC1_OFF)
#define G_HB   (g_scratch + HB_OFF)
#define G_QC2  (g_scratch + QC2_OFF)
#define G_AV   (g_scratch + AV_OFF)
#define G_CENT ((int*)(g_scratch + CENT_OFF))

// ---------------------------------------------------------------------------
// f32x2 packed helpers
// ---------------------------------------------------------------------------
__device__ __forceinline__ ull pack2(float x, float y) {
    ull r; asm("mov.b64 %0, {%1,%2};" : "=l"(r) : "f"(x), "f"(y)); return r;
}
__device__ __forceinline__ float2 unpack2(ull v) {
    float2 f; asm("mov.b64 {%0,%1}, %2;" : "=f"(f.x), "=f"(f.y) : "l"(v)); return f;
}
__device__ __forceinline__ void fma2(ull& d, ull a, ull b) {
    asm("fma.rn.f32x2 %0, %1, %2, %0;" : "+l"(d) : "l"(a), "l"(b));
}

__device__ __forceinline__ float gelu_f(float x) {
    return 0.5f * x * (1.0f + erff(x * 0.70710678118654752f));
}

// ---------------------------------------------------------------------------
// K0: LayerNorm. One block per row, 128 threads, 3 elems/thread.
// ---------------------------------------------------------------------------
__global__ void ln_kernel(const float* __restrict__ x,
                          const float* __restrict__ w,
                          const float* __restrict__ b) {
    int row = blockIdx.x;
    const float* xr = x + (size_t)row * C_;
    int tid = threadIdx.x;
    float v[3];
    float s = 0.f, sq = 0.f;
#pragma unroll
    for (int i = 0; i < 3; i++) {
        v[i] = xr[tid + 128 * i];
        s += v[i]; sq += v[i] * v[i];
    }
#pragma unroll
    for (int o = 16; o; o >>= 1) {
        s  += __shfl_xor_sync(0xffffffffu, s, o);
        sq += __shfl_xor_sync(0xffffffffu, sq, o);
    }
    __shared__ float ss[4], ssq[4];
    if ((tid & 31) == 0) { ss[tid >> 5] = s; ssq[tid >> 5] = sq; }
    __syncthreads();
    s  = ss[0] + ss[1] + ss[2] + ss[3];
    sq = ssq[0] + ssq[1] + ssq[2] + ssq[3];
    float mu = s * (1.0f / C_);
    float var = sq * (1.0f / C_) - mu * mu;
    float rstd = rsqrtf(var + EPS_);
    float* orow = G_XN + (size_t)row * C_;
#pragma unroll
    for (int i = 0; i < 3; i++) {
        int c = tid + 128 * i;
        orow[c] = (v[i] - mu) * rstd * w[c] + b[c];
    }
}

// ---------------------------------------------------------------------------
// GEMM: C[M,Nn] = A[M,K] @ W[Nn,K]^T (+bias)(+gelu)
// 128x128x16 tile, 256 threads, 8x8 microtile, f32x2 math,
// register-staged double-buffered smem.
// NEW lane map (vs R3): within-warp 4m x 8n (r=lane>>3, c=lane&7);
// warp tile 32m x 64n (wm=warp&3, wn=warp>>2). A LDS.128 spans ONE 128B
// line (1 wavefront), B spans 256B (2 wavefronts): 6 wf/warp-kk vs 10.
// Flips the kernel from smem-crossbar-bound to fma-bound.
// ---------------------------------------------------------------------------
#define BM 128
#define BN 128
#define BK 16

__device__ __forceinline__
void gemm_body(const float* __restrict__ A, const float* __restrict__ W,
               const float* __restrict__ bias, float* __restrict__ Cm,
               int M, int Nn, int K, int epi) {
    __shared__ __align__(16) float As[2][BK][BM];
    __shared__ __align__(16) float Bs[2][BK][BN];
    int tid = threadIdx.x;
    int lane = tid & 31, warp = tid >> 5;
    int m_t = (warp & 3) * 32 + (lane >> 3) * 8;   // thread's 8-row block
    int n_t = (warp >> 2) * 64 + (lane & 7) * 8;   // thread's 8-col block
    int m0 = blockIdx.y * BM, n0 = blockIdx.x * BN;

    int lr = tid >> 1;
    int lc = (tid & 1) * 8;
    const float* Aptr = A + (size_t)(m0 + lr) * K + lc;
    const float* Wptr = W + (size_t)(n0 + lr) * K + lc;

    ull acc[8][4];
#pragma unroll
    for (int i = 0; i < 8; i++)
#pragma unroll
        for (int j = 0; j < 4; j++) acc[i][j] = 0ull;

    float4 a0 = *(const float4*)(Aptr + 0);
    float4 a1 = *(const float4*)(Aptr + 4);
    float4 b0 = *(const float4*)(Wptr + 0);
    float4 b1 = *(const float4*)(Wptr + 4);
    As[0][lc + 0][lr] = a0.x; As[0][lc + 1][lr] = a0.y;
    As[0][lc + 2][lr] = a0.z; As[0][lc + 3][lr] = a0.w;
    As[0][lc + 4][lr] = a1.x; As[0][lc + 5][lr] = a1.y;
    As[0][lc + 6][lr] = a1.z; As[0][lc + 7][lr] = a1.w;
    Bs[0][lc + 0][lr] = b0.x; Bs[0][lc + 1][lr] = b0.y;
    Bs[0][lc + 2][lr] = b0.z; Bs[0][lc + 3][lr] = b0.w;
    Bs[0][lc + 4][lr] = b1.x; Bs[0][lc + 5][lr] = b1.y;
    Bs[0][lc + 6][lr] = b1.z; Bs[0][lc + 7][lr] = b1.w;
    __syncthreads();

    int nk = K / BK;
    for (int kt = 0; kt < nk; kt++) {
        int cur = kt & 1;
        if (kt + 1 < nk) {
            const float* Ap = Aptr + (kt + 1) * BK;
            const float* Wp = Wptr + (kt + 1) * BK;
            a0 = *(const float4*)(Ap + 0);
            a1 = *(const float4*)(Ap + 4);
            b0 = *(const float4*)(Wp + 0);
            b1 = *(const float4*)(Wp + 4);
        }
#pragma unroll
        for (int kk = 0; kk < BK; kk++) {
            float4 av0 = *(const float4*)&As[cur][kk][m_t];
            float4 av1 = *(const float4*)&As[cur][kk][m_t + 4];
            float4 bv0 = *(const float4*)&Bs[cur][kk][n_t];
            float4 bv1 = *(const float4*)&Bs[cur][kk][n_t + 4];
            ull bp0 = pack2(bv0.x, bv0.y);
            ull bp1 = pack2(bv0.z, bv0.w);
            ull bp2 = pack2(bv1.x, bv1.y);
            ull bp3 = pack2(bv1.z, bv1.w);
            float am[8] = {av0.x, av0.y, av0.z, av0.w,
                           av1.x, av1.y, av1.z, av1.w};
#pragma unroll
            for (int i = 0; i < 8; i++) {
                ull ap = pack2(am[i], am[i]);
                fma2(acc[i][0], ap, bp0);
                fma2(acc[i][1], ap, bp1);
                fma2(acc[i][2], ap, bp2);
                fma2(acc[i][3], ap, bp3);
            }
        }
        if (kt + 1 < nk) {
            int nxt = 1 - cur;
            As[nxt][lc + 0][lr] = a0.x; As[nxt][lc + 1][lr] = a0.y;
            As[nxt][lc + 2][lr] = a0.z; As[nxt][lc + 3][lr] = a0.w;
            As[nxt][lc + 4][lr] = a1.x; As[nxt][lc + 5][lr] = a1.y;
            As[nxt][lc + 6][lr] = a1.z; As[nxt][lc + 7][lr] = a1.w;
            Bs[nxt][lc + 0][lr] = b0.x; Bs[nxt][lc + 1][lr] = b0.y;
            Bs[nxt][lc + 2][lr] = b0.z; Bs[nxt][lc + 3][lr] = b0.w;
            Bs[nxt][lc + 4][lr] = b1.x; Bs[nxt][lc + 5][lr] = b1.y;
            Bs[nxt][lc + 6][lr] = b1.z; Bs[nxt][lc + 7][lr] = b1.w;
            __syncthreads();
        }
    }

    int gn = n0 + n_t;
    float bb[8];
#pragma unroll
    for (int j = 0; j < 8; j++) bb[j] = bias ? bias[gn + j] : 0.f;
#pragma unroll
    for (int i = 0; i < 8; i++) {
        int gm = m0 + m_t + i;
        float o[8];
#pragma unroll
        for (int j = 0; j < 4; j++) {
            float2 c = unpack2(acc[i][j]);
            o[2 * j] = c.x + bb[2 * j];
            o[2 * j + 1] = c.y + bb[2 * j + 1];
        }
        if (epi == 1) {
#pragma unroll
            for (int j = 0; j < 8; j++) o[j] = gelu_f(o[j]);
        }
        float4 w0 = {o[0], o[1], o[2], o[3]};
        float4 w1 = {o[4], o[5], o[6], o[7]};
        *(float4*)(Cm + (size_t)gm * Nn + gn) = w0;
        *(float4*)(Cm + (size_t)gm * Nn + gn + 4) = w1;
    }
}

__global__ __launch_bounds__(256, 2) void gemm_xn_kv(const float* __restrict__ kv_w) {
    gemm_body(G_XN, kv_w, nullptr, G_KV, B_ * N_, 2 * C_, C_, 0);
}
__global__ __launch_bounds__(256, 2) void gemm_qc1_hb(const float* __restrict__ w,
                                                      const float* __restrict__ b) {
    gemm_body(G_QC1, w, b, G_HB, B_ * NT_, 2 * C_, C_, 1);
}
__global__ __launch_bounds__(256, 2) void gemm_hb_qc2(const float* __restrict__ w,
                                                      const float* __restrict__ b) {
    gemm_body(G_HB, w, b, G_QC2, B_ * NT_, C_, 2 * C_, 0);
}
__global__ __launch_bounds__(256, 2) void gemm_av_out(const float* __restrict__ w,
                                                      const float* __restrict__ b,
                                                      float* __restrict__ out) {
    gemm_body(G_AV, w, b, out, B_ * NT_, C_, C_, 0);
}

// ---------------------------------------------------------------------------
// K2: attn1 + q_cond1. One block per (b,h). (R3-identical.)
// ---------------------------------------------------------------------------
#define ATTN1_SMEM (3 * NT_ * HD_ * 4)

__global__ __launch_bounds__(256)
void attn1_kernel(const float* __restrict__ qg, const int* __restrict__ idx_sub) {
    extern __shared__ float sh[];
    float* qs = sh;
    float* ks = sh + NT_ * HD_;
    float* vs = sh + 2 * NT_ * HD_;
    int b = blockIdx.x >> 3;
    int h = blockIdx.x & 7;
    int tid = threadIdx.x;

    for (int i = tid; i < NT_ * HD_; i += 256) {
        int n = i / HD_, d = i % HD_;
        qs[i] = qg[((size_t)n * H_ + h) * HD_ + d];
        int src = idx_sub[n];
        const float* kvrow = G_KV + ((size_t)b * N_ + src) * (2 * C_) + h * HD_ + d;
        ks[i] = kvrow[0];
        vs[i] = kvrow[C_];
    }
    __syncthreads();

    int m = tid;
    if (m < NT_) {
        float sc[NT_];
        float mx = -1e30f;
        const float* qm = qs + m * HD_;
        for (int n = 0; n < NT_; n++) {
            const float* kn = ks + n * HD_;
            float s = 0.f;
#pragma unroll
            for (int d = 0; d < HD_; d++) s += qm[d] * kn[d];
            s *= SCALE_;
            sc[n] = s;
            mx = fmaxf(mx, s);
        }
        float sum = 0.f;
        for (int n = 0; n < NT_; n++) {
            float e = expf(sc[n] - mx);
            sc[n] = e; sum += e;
        }
        float inv = 1.0f / sum;
        float accv[HD_];
#pragma unroll
        for (int d = 0; d < HD_; d++) accv[d] = 0.f;
        for (int n = 0; n < NT_; n++) {
            float wgt = sc[n];
            const float* vn = vs + n * HD_;
#pragma unroll
            for (int d = 0; d < HD_; d++) accv[d] += wgt * vn[d];
        }
        float* orow = G_QC1 + ((size_t)b * NT_ + m) * C_ + h * HD_;
#pragma unroll
        for (int d = 0; d < HD_; d++) orow[d] = accv[d] * inv;
    }
}

// ---------------------------------------------------------------------------
// K5: attn2 mean-over-heads + argmax (R3-identical; tiling was neutral).
// ---------------------------------------------------------------------------
#define MCH 7
__global__ __launch_bounds__(256)
void attn2_kernel(const int* __restrict__ idxs) {
    int b = blockIdx.x / 28;
    int m0 = (blockIdx.x % 28) * MCH;
    __shared__ float qsh[MCH * C_];
    __shared__ float krow[C_];
    __shared__ int sIdxs[NT_];
    int tid = threadIdx.x;
    for (int i = tid; i < MCH * C_; i += 256)
        qsh[i] = G_QC2[((size_t)b * NT_ + m0) * C_ + i];
    for (int i = tid; i < NT_; i += 256) sIdxs[i] = idxs[i];
    int warp = tid >> 5, lane = tid & 31;
    float best = -1e30f;
    int bestn = 0;
    __syncthreads();
    for (int n = 0; n < NT_; n++) {
        __syncthreads();
        for (int i = tid; i < C_; i += 256)
            krow[i] = G_KV[((size_t)b * N_ + sIdxs[n]) * (2 * C_) + i];
        __syncthreads();
        if (warp < MCH) {
            const float* qm = qsh + warp * C_;
            float p = 0.f;
#pragma unroll
            for (int j = 0; j < 12; j++) p += qm[lane + 32 * j] * krow[lane + 32 * j];
#pragma unroll
            for (int o = 16; o; o >>= 1) p += __shfl_xor_sync(0xffffffffu, p, o);
            if (p > best) { best = p; bestn = n; }
        }
    }
    if (warp < MCH && lane == 0)
        G_CENT[(size_t)b * NT_ + m0 + warp] = sIdxs[bestn];
}

// ---------------------------------------------------------------------------
// K6: masked attn3 (sparse over deduped adjusted-index set). (R3-identical.)
// ---------------------------------------------------------------------------
__global__ __launch_bounds__(256)
void attn3_kernel() {
    int bm = blockIdx.x;
    int b = bm / NT_;
    __shared__ unsigned int bmap[N_ / 32];
    __shared__ int sIdx[169];
    __shared__ int cnt;
    __shared__ float sQ[C_];
    __shared__ float sS[H_][169];
    int tid = threadIdx.x;
    if (tid < N_ / 32) bmap[tid] = 0u;
    if (tid == 0) cnt = 0;
    __syncthreads();
    int ci = G_CENT[bm];
    if (tid < 169) {
        int row = tid / 13 - 6;
        int col = tid % 13 - 6;
        int adj = ci + (col - 56 * row);
        adj = max(0, min(N_ - 1, adj));
        atomicOr(&bmap[adj >> 5], 1u << (adj & 31));
    }
    for (int i = tid; i < C_; i += 256)
        sQ[i] = G_QC2[(size_t)bm * C_ + i] * SCALE_;
    __syncthreads();
    if (tid < N_ / 32) {
        unsigned int w = bmap[tid];
        if (w) {
            int base = atomicAdd(&cnt, __popc(w));
            int off = 0;
            while (w) {
                int bit = __ffs(w) - 1;
                w &= w - 1;
                sIdx[base + off] = (tid << 5) + bit;
                off++;
            }
        }
    }
    __syncthreads();
    int count = cnt;
    int h = tid >> 5, lane = tid & 31;
    const float* qh = sQ + h * HD_;
    float mx = -1e30f;
    for (int e = 0; e < count; e++) {
        const float* kr = G_KV + ((size_t)b * N_ + sIdx[e]) * (2 * C_) + h * HD_;
        float p = kr[lane] * qh[lane];
        if (lane < 16) p += kr[lane + 32] * qh[lane + 32];
#pragma unroll
        for (int o = 16; o; o >>= 1) p += __shfl_xor_sync(0xffffffffu, p, o);
        if (lane == 0) sS[h][e] = p;
        mx = fmaxf(mx, p);
    }
    __syncwarp();
    float sum = 0.f;
    for (int e = lane; e < count; e += 32) {
        float ee = expf(sS[h][e] - mx);
        sS[h][e] = ee;
        sum += ee;
    }
#pragma unroll
    for (int o = 16; o; o >>= 1) sum += __shfl_xor_sync(0xffffffffu, sum, o);
    float inv = 1.0f / sum;
    __syncwarp();
    float a0 = 0.f, a1 = 0.f;
    for (int e = 0; e < count; e++) {
        float wgt = sS[h][e];
        const float* vr = G_KV + ((size_t)b * N_ + sIdx[e]) * (2 * C_) + C_ + h * HD_;
        a0 += wgt * vr[lane];
        if (lane < 16) a1 += wgt * vr[lane + 32];
    }
    float* orow = G_AV + (size_t)bm * C_ + h * HD_;
    orow[lane] = a0 * inv;
    if (lane < 16) orow[lane + 32] = a1 * inv;
}

// ---------------------------------------------------------------------------
// Launch: kernel launches only.
// ---------------------------------------------------------------------------
extern "C" void kernel_launch(void* const* d_in, const int* in_sizes, int n_in,
                              void* d_out, int out_size) {
    const float* x      = (const float*)d_in[0];
    const float* q      = (const float*)d_in[1];
    const float* kv_w   = (const float*)d_in[2];
    const float* proj_w = (const float*)d_in[3];
    const float* proj_b = (const float*)d_in[4];
    const float* ln_w   = (const float*)d_in[5];
    const float* ln_b   = (const float*)d_in[6];
    const float* fc1_w  = (const float*)d_in[7];
    const float* fc1_b  = (const float*)d_in[8];
    const float* fc2_w  = (const float*)d_in[9];
    const float* fc2_b  = (const float*)d_in[10];
    const int* idx_sub  = (const int*)d_in[11];
    const int* idxs     = (const int*)d_in[12];
    float* out = (float*)d_out;

    cudaFuncSetAttribute(attn1_kernel,
                         cudaFuncAttributeMaxDynamicSharedMemorySize, ATTN1_SMEM);

    // K0: LayerNorm -> G_XN
    ln_kernel<<<B_ * N_, 128>>>(x, ln_w, ln_b);

    // K1: KV projection (dominant GEMM, fp32-exact)
    {
        dim3 g(2 * C_ / BN, (B_ * N_) / BM);
        gemm_xn_kv<<<g, 256>>>(kv_w);
    }

    // K2: attn1 -> G_QC1
    attn1_kernel<<<B_ * H_, 256, ATTN1_SMEM>>>(q, idx_sub);

    // K3: fc1 + gelu -> G_HB
    {
        dim3 g(2 * C_ / BN, (B_ * NT_) / BM);
        gemm_qc1_hb<<<g, 256>>>(fc1_w, fc1_b);
    }
    // K4: fc2 -> G_QC2
    {
        dim3 g(C_ / BN, (B_ * NT_) / BM);
        gemm_hb_qc2<<<g, 256>>>(fc2_w, fc2_b);
    }

    // K5: attn2 + argmax -> G_CENT
    attn2_kernel<<<B_ * 28, 256>>>(idxs);

    // K6: sparse masked attn3 -> G_AV
    attn3_kernel<<<B_ * NT_, 256>>>();

    // K7: output projection -> d_out
    {
        dim3 g(C_ / BN, (B_ * NT_) / BM);
        gemm_av_out<<<g, 256>>>(proj_w, proj_b, out);
    }
}